// round 16
// baseline (speedup 1.0000x reference)
#include <cuda_runtime.h>
#include <cuda_bf16.h>
#include <cuda_fp16.h>
#include <math.h>
#include <stdint.h>

#define VV 2
#define KK 8
#define DD 128
#define TN 128
#define AST 132
#define LOG2PI_F 1.8378770664093453f

__device__ uint32_t g_Bfrag[VV * KK * 9216];
__device__ float g_u[VV * KK * DD];
__device__ float g_logc[VV * KK];
__device__ float g_pen[VV * KK];
__device__ int g_ticket;

__device__ __forceinline__ void split_f16(float x, unsigned short& h, unsigned short& l) {
    __half hb = __float2half_rn(x);
    float r = x - __half2float(hb);
    __half lb = __float2half_rn(r);
    h = __half_as_ushort(hb);
    l = __half_as_ushort(lb);
}

// f16 inputs, f32 accumulate
#define MMA16816H(c, a, b)                                                     \
    asm volatile(                                                              \
        "mma.sync.aligned.m16n8k16.row.col.f32.f16.f16.f32 "                   \
        "{%0,%1,%2,%3}, {%4,%5,%6,%7}, {%8,%9}, {%0,%1,%2,%3};"                \
        : "+f"((c)[0]), "+f"((c)[1]), "+f"((c)[2]), "+f"((c)[3])               \
        : "r"((a)[0]), "r"((a)[1]), "r"((a)[2]), "r"((a)[3]),                  \
          "r"((b).x), "r"((b).y))

// f16 inputs, f16 accumulate (2x-rate pipe)
#define MMA16816HH(c, a, b)                                                    \
    asm volatile(                                                              \
        "mma.sync.aligned.m16n8k16.row.col.f16.f16.f16.f16 "                   \
        "{%0,%1}, {%2,%3,%4,%5}, {%6,%7}, {%0,%1};"                            \
        : "+r"((c)[0]), "+r"((c)[1])                                           \
        : "r"((a)[0]), "r"((a)[1]), "r"((a)[2]), "r"((a)[3]),                  \
          "r"((b).x), "r"((b).y))

// ---------------------------------------------------------------------------
// setup (R15): 512 threads, LDL^T 4-way split, blocked unit-lower inverse.
// ---------------------------------------------------------------------------
__global__ void __launch_bounds__(512)
setup_kernel(const float* __restrict__ phi,
             const float* __restrict__ mu,
             const float* __restrict__ sigma,
             float* __restrict__ out, int Npts) {
    extern __shared__ float sm[];
    float (*A)[AST] = (float (*)[AST])sm;
    float (*M)[AST] = (float (*)[AST])(sm + DD * AST);
    float* red = sm + 2 * DD * AST;
    float* dinv = red + DD;
    float* scl = dinv + DD;
    float* mus = scl + DD;
    float* Tb = mus + DD;

    const int tid = threadIdx.x;
    const int t = tid & 127;
    const int h = tid >> 7;
    const int v = blockIdx.x / KK;
    const int k = blockIdx.x % KK;
    const float* S = sigma + (size_t)(v * KK + k) * DD * DD;

    if (blockIdx.x == 0 && tid == 0) {
        out[(size_t)4 * Npts] = 0.0f;
        g_ticket = 0;
    }

    for (int idx = tid; idx < DD * DD; idx += 512)
        A[idx >> 7][idx & 127] = S[idx];
    __syncthreads();

    if (tid < DD) {
        float dg = A[tid][tid] + 1e-6f;
        A[tid][tid] = dg;
        red[tid] = 1.0f / (dg + 1e-12f);
    }
    __syncthreads();
    for (int s = 64; s > 0; s >>= 1) {
        if (tid < s) red[tid] += red[tid + s];
        __syncthreads();
    }
    if (tid == 0) g_pen[v * KK + k] = red[0];
    __syncthreads();

    for (int j = 0; j < DD; j++) {
        float invd = __fdividef(1.0f, A[j][j]);
        int n = t - j;
        if (n > 0) {
            float mf = -A[t][j] * invd;
            int q = (n + 3) >> 2;
            int lo = j + 1 + h * q;
            int hi = j + (h + 1) * q;
            if (hi > t) hi = t;
            int l = lo;
            for (; l <= hi && (l & 3); l++)
                A[t][l] = fmaf(mf, A[l][j], A[t][l]);
            for (; l + 3 <= hi; l += 4) {
                float4 av = *(float4*)&A[t][l];
                av.x = fmaf(mf, A[l][j], av.x);
                av.y = fmaf(mf, A[l + 1][j], av.y);
                av.z = fmaf(mf, A[l + 2][j], av.z);
                av.w = fmaf(mf, A[l + 3][j], av.w);
                *(float4*)&A[t][l] = av;
            }
            for (; l <= hi; l++)
                A[t][l] = fmaf(mf, A[l][j], A[t][l]);
        }
        __syncthreads();
    }

    if (tid < DD) {
        float d = A[tid][tid];
        red[tid] = logf(d);
        dinv[tid] = __fdividef(1.0f, d);
        scl[tid] = rsqrtf(d);
    }
    __syncthreads();
    for (int s = 64; s > 0; s >>= 1) {
        if (tid < s) red[tid] += red[tid + s];
        __syncthreads();
    }
    float logdet = fmaxf(red[0], logf(1e-6f));
    __syncthreads();

    for (int idx = tid; idx < DD * DD; idx += 512)
        M[idx >> 7][idx & 127] = 0.0f;
    __syncthreads();

    if (tid < DD) {
        const int q = tid >> 5;
        const int c = tid & 31;
        const int base = q * 32;
        M[base + c][base + c] = 1.0f;
        for (int j = c + 1; j < 32; j++) {
            float s = 0.0f;
            for (int i = c; i < j; i++)
                s = fmaf(A[base + j][base + i] * dinv[base + i],
                         M[base + i][base + c], s);
            M[base + j][base + c] = -s;
        }
    }
    __syncthreads();

    if (tid < 256) {
        const int row = tid >> 3;
        const int c0 = (tid & 7) * 4;
        for (int d = 1; d < 4; d++) {
            const int nb = 4 - d;
            for (int b = 0; b < nb; b++) {
                const int p = b + d, q = b;
                float s0 = 0.0f, s1 = 0.0f, s2 = 0.0f, s3 = 0.0f;
                for (int r = q; r < p; r++) {
#pragma unroll 8
                    for (int i = 0; i < 32; i++) {
                        float a = A[p * 32 + row][r * 32 + i] * dinv[r * 32 + i];
                        const float* mr = &M[r * 32 + i][q * 32 + c0];
                        s0 = fmaf(a, mr[0], s0);
                        s1 = fmaf(a, mr[1], s1);
                        s2 = fmaf(a, mr[2], s2);
                        s3 = fmaf(a, mr[3], s3);
                    }
                }
                float* tr = &Tb[b * 1056 + row * 33 + c0];
                tr[0] = s0; tr[1] = s1; tr[2] = s2; tr[3] = s3;
                __syncwarp();
            }
            asm volatile("bar.sync 1, 256;" ::: "memory");
            for (int b = 0; b < nb; b++) {
                const int p = b + d, q = b;
                float s0 = 0.0f, s1 = 0.0f, s2 = 0.0f, s3 = 0.0f;
                for (int i = 0; i <= row; i++) {
                    float a = M[p * 32 + row][p * 32 + i];
                    const float* tr = &Tb[b * 1056 + i * 33 + c0];
                    s0 = fmaf(a, tr[0], s0);
                    s1 = fmaf(a, tr[1], s1);
                    s2 = fmaf(a, tr[2], s2);
                    s3 = fmaf(a, tr[3], s3);
                }
                float* mr = &M[p * 32 + row][q * 32 + c0];
                mr[0] = -s0; mr[1] = -s1; mr[2] = -s2; mr[3] = -s3;
            }
            asm volatile("bar.sync 1, 256;" ::: "memory");
        }
    }
    __syncthreads();

    if (tid < DD) mus[tid] = mu[(size_t)(v * KK + k) * DD + tid];
    __syncthreads();
    if (tid < DD) {
        float u = 0.0f;
        const float4* mr = (const float4*)&M[tid][0];
        const float4* mv = (const float4*)mus;
        for (int j = 0; j < DD / 4; j++) {
            float4 a = mr[j], b = mv[j];
            u = fmaf(a.x, b.x, u);
            u = fmaf(a.y, b.y, u);
            u = fmaf(a.z, b.z, u);
            u = fmaf(a.w, b.w, u);
        }
        g_u[(size_t)(v * KK + k) * DD + tid] = u * scl[tid];
    }

    uint32_t* blob = g_Bfrag + (size_t)(v * KK + k) * 9216;
    for (int idx = tid; idx < 9216; idx += 512) {
        int reg = idx & 1;
        int lane = (idx >> 1) & 31;
        int hl = (idx >> 6) & 1;
        int ws = idx >> 7;
        int w = ws / 9;
        int s = ws - w * 9;
        int nA = (w >> 1) + 1;
        int b = (s < nA) ? w : 15 - w;
        int kb = (s < nA) ? s : s - nA;
        int col = b * 8 + (lane >> 2);
        int k0 = kb * 16 + (lane & 3) * 2 + reg * 8;
        float sc = scl[col];
        unsigned short h0, l0, h1, l1;
        split_f16(M[col][k0] * sc, h0, l0);
        split_f16(M[col][k0 + 1] * sc, h1, l1);
        blob[idx] = hl ? ((uint32_t)l0 | ((uint32_t)l1 << 16))
                       : ((uint32_t)h0 | ((uint32_t)h1 << 16));
    }

    if (tid == 0) {
        float pm = -3.0e38f;
        for (int i = 0; i < KK; i++) pm = fmaxf(pm, phi[v * KK + i]);
        float se = 0.0f;
        for (int i = 0; i < KK; i++) se += expf(phi[v * KK + i] - pm);
        float logpi = phi[v * KK + k] - pm - logf(se);
        g_logc[v * KK + k] = logpi - 0.5f * (float)DD * LOG2PI_F - 0.5f * logdet;
    }
}

// ---------------------------------------------------------------------------
// mainloop: hh pass f16->f32 acc; hl+lh correction passes f16->f16 acc.
// ---------------------------------------------------------------------------
template <int NA>
__device__ __forceinline__ void view_mainloop(
    const uint32_t* __restrict__ Bg, const uint32_t* __restrict__ Ah,
    float* __restrict__ slab, const float* __restrict__ us,
    int w, int lane) {
    constexpr int NB = 9 - NA;
    const int tq = lane & 3;
    const int tr = lane >> 2;

    uint2 BfA[NA][2], BfB[NB][2];
    {
        const uint32_t* bc = Bg + w * 9 * 128 + lane * 2;
#pragma unroll
        for (int s = 0; s < NA; s++) {
            BfA[s][0] = *(const uint2*)(bc + (s * 2 + 0) * 64);
            BfA[s][1] = *(const uint2*)(bc + (s * 2 + 1) * 64);
        }
#pragma unroll
        for (int s = 0; s < NB; s++) {
            BfB[s][0] = *(const uint2*)(bc + ((NA + s) * 2 + 0) * 64);
            BfB[s][1] = *(const uint2*)(bc + ((NA + s) * 2 + 1) * 64);
        }
    }

    for (int comp = 0; comp < KK; comp++) {
        const float* uc = us + comp * DD;
        const float uA0 = uc[w * 8 + tq * 2];
        const float uA1 = uc[w * 8 + tq * 2 + 1];
        const float uB0 = uc[(15 - w) * 8 + tq * 2];
        const float uB1 = uc[(15 - w) * 8 + tq * 2 + 1];

#pragma unroll
        for (int rbc = 0; rbc < 2; rbc++) {
            float accA[4][4], accB[4][4];
            uint32_t accAc[4][2], accBc[4][2];
#pragma unroll
            for (int r4 = 0; r4 < 4; r4++) {
#pragma unroll
                for (int r = 0; r < 4; r++) {
                    accA[r4][r] = 0.0f;
                    accB[r4][r] = 0.0f;
                }
                accAc[r4][0] = 0u; accAc[r4][1] = 0u;
                accBc[r4][0] = 0u; accBc[r4][1] = 0u;
            }

#pragma unroll
            for (int kb = 0; kb < NB; kb++) {
                uint32_t a[4][4], al[4][4];
#pragma unroll
                for (int r4 = 0; r4 < 4; r4++) {
                    const uint32_t* ap =
                        Ah + ((rbc * 4 + r4) * 8 + kb) * 128 + lane * 4;
                    uint4 av = *(const uint4*)ap;
                    uint4 lv = *(const uint4*)(ap + 8192);
                    a[r4][0] = av.x; a[r4][1] = av.y;
                    a[r4][2] = av.z; a[r4][3] = av.w;
                    al[r4][0] = lv.x; al[r4][1] = lv.y;
                    al[r4][2] = lv.z; al[r4][3] = lv.w;
                }
                // hh: f32 accumulate
#pragma unroll
                for (int r4 = 0; r4 < 4; r4++)
                    MMA16816H(accB[r4], a[r4], BfB[kb][0]);
                if (kb < NA) {
#pragma unroll
                    for (int r4 = 0; r4 < 4; r4++)
                        MMA16816H(accA[r4], a[r4], BfA[kb][0]);
                }
                // hl: f16 accumulate
#pragma unroll
                for (int r4 = 0; r4 < 4; r4++)
                    MMA16816HH(accBc[r4], a[r4], BfB[kb][1]);
                if (kb < NA) {
#pragma unroll
                    for (int r4 = 0; r4 < 4; r4++)
                        MMA16816HH(accAc[r4], a[r4], BfA[kb][1]);
                }
                // lh: f16 accumulate
#pragma unroll
                for (int r4 = 0; r4 < 4; r4++)
                    MMA16816HH(accBc[r4], al[r4], BfB[kb][0]);
                if (kb < NA) {
#pragma unroll
                    for (int r4 = 0; r4 < 4; r4++)
                        MMA16816HH(accAc[r4], al[r4], BfA[kb][0]);
                }
            }

#pragma unroll
            for (int r4 = 0; r4 < 4; r4++) {
                const int rb = rbc * 4 + r4;
                float2 cA0 = __half22float2(*(__half2*)&accAc[r4][0]);
                float2 cA1 = __half22float2(*(__half2*)&accAc[r4][1]);
                float2 cB0 = __half22float2(*(__half2*)&accBc[r4][0]);
                float2 cB1 = __half22float2(*(__half2*)&accBc[r4][1]);
                float d0 = (accA[r4][0] + cA0.x) - uA0;
                float d1 = (accA[r4][1] + cA0.y) - uA1;
                float d2 = (accB[r4][0] + cB0.x) - uB0;
                float d3 = (accB[r4][1] + cB0.y) - uB1;
                float s0 = d0 * d0 + d1 * d1 + d2 * d2 + d3 * d3;
                float e0 = (accA[r4][2] + cA1.x) - uA0;
                float e1 = (accA[r4][3] + cA1.y) - uA1;
                float e2 = (accB[r4][2] + cB1.x) - uB0;
                float e3 = (accB[r4][3] + cB1.y) - uB1;
                float s1 = e0 * e0 + e1 * e1 + e2 * e2 + e3 * e3;
                s0 += __shfl_xor_sync(0xffffffffu, s0, 1);
                s0 += __shfl_xor_sync(0xffffffffu, s0, 2);
                s1 += __shfl_xor_sync(0xffffffffu, s1, 1);
                s1 += __shfl_xor_sync(0xffffffffu, s1, 2);
                if (tq == 0) {
                    slab[w * 1024 + (rb * 16 + tr) * 8 + comp] = s0;
                    slab[w * 1024 + (rb * 16 + tr + 8) * 8 + comp] = s1;
                }
            }
        }

        if (comp + 1 < KK) {
            const uint32_t* bc =
                Bg + (size_t)(comp + 1) * 9216 + w * 9 * 128 + lane * 2;
#pragma unroll
            for (int s = 0; s < NA; s++) {
                BfA[s][0] = *(const uint2*)(bc + (s * 2 + 0) * 64);
                BfA[s][1] = *(const uint2*)(bc + (s * 2 + 1) * 64);
            }
#pragma unroll
            for (int s = 0; s < NB; s++) {
                BfB[s][0] = *(const uint2*)(bc + ((NA + s) * 2 + 0) * 64);
                BfB[s][1] = *(const uint2*)(bc + ((NA + s) * 2 + 1) * 64);
            }
        }
    }
}

// ---------------------------------------------------------------------------
// main: persistent, per-tile ticket, views fused, weights in main.
// ---------------------------------------------------------------------------
__global__ void __launch_bounds__(256)
main_kernel(const float* __restrict__ z, float* __restrict__ out,
            int Npts, int ntiles) {
    extern __shared__ __align__(16) unsigned char smraw[];
    uint32_t* Ah = (uint32_t*)smraw;
    float* slab = (float*)(smraw + 65536);
    float* us = (float*)(smraw + 98304);
    float* mah = (float*)(smraw + 102400);
    __shared__ int s_tile;
    __shared__ float wsum[8];

    const int tid = threadIdx.x;
    const int w = tid >> 5;
    const int lane = tid & 31;

    if (blockIdx.x == 0 && tid == 0) {
        float p = 0.0f;
#pragma unroll
        for (int i = 0; i < VV * KK; i++) p += g_pen[i];
        out[(size_t)4 * Npts + 1] = p;
    }

    float esum = 0.0f;

    for (;;) {
        if (tid == 0) s_tile = atomicAdd(&g_ticket, 1);
        __syncthreads();
        const int tile = s_tile;
        if (tile >= ntiles) break;
        const int n0 = tile * TN;

        float e_prev = 0.0f;

        for (int v = 0; v < VV; v++) {
            const uint32_t* Bg = g_Bfrag + (size_t)v * KK * 9216;

            for (int i = tid; i < KK * DD; i += 256)
                us[i] = g_u[(size_t)v * KK * DD + i];

            const float* zr = z + (size_t)v * Npts * DD;
#pragma unroll
            for (int it = 0; it < 8; it++) {
                int idx = tid + it * 256;
                int p = idx >> 4;
                int oct = idx & 15;
                int n = n0 + p;
                float f[8];
                if (n < Npts) {
                    const float4* src =
                        (const float4*)(zr + (size_t)n * DD + oct * 8);
                    float4 a = src[0], b = src[1];
                    f[0] = a.x; f[1] = a.y; f[2] = a.z; f[3] = a.w;
                    f[4] = b.x; f[5] = b.y; f[6] = b.z; f[7] = b.w;
                } else {
#pragma unroll
                    for (int j = 0; j < 8; j++) f[j] = 0.0f;
                }
                int rb = p >> 4;
                int row_in = p & 15;
                int lane_row = row_in & 7;
                int rbit = row_in >> 3;
                int kb = oct >> 1;
                int khalf = oct & 1;
                int reg = (khalf << 1) | rbit;
                uint32_t base = (uint32_t)((rb * 8 + kb) * 128 + reg);
#pragma unroll
                for (int j = 0; j < 4; j++) {
                    unsigned short h0, l0, h1, l1;
                    split_f16(f[2 * j], h0, l0);
                    split_f16(f[2 * j + 1], h1, l1);
                    uint32_t off = base + (uint32_t)(lane_row * 4 + j) * 4;
                    Ah[off] = (uint32_t)h0 | ((uint32_t)h1 << 16);
                    Ah[off + 8192] = (uint32_t)l0 | ((uint32_t)l1 << 16);
                }
            }
            __syncthreads();

            switch (w >> 1) {
                case 0: view_mainloop<1>(Bg, Ah, slab, us, w, lane); break;
                case 1: view_mainloop<2>(Bg, Ah, slab, us, w, lane); break;
                case 2: view_mainloop<3>(Bg, Ah, slab, us, w, lane); break;
                default: view_mainloop<4>(Bg, Ah, slab, us, w, lane); break;
            }
            __syncthreads();

            for (int i = tid; i < TN * KK; i += 256) {
                float s = 0.0f;
#pragma unroll
                for (int ww = 0; ww < 8; ww++) s += slab[ww * 1024 + i];
                mah[i] = s;
            }
            __syncthreads();

            if (tid < TN) {
                int n = n0 + tid;
                if (n < Npts) {
                    float lp[KK];
                    float m = -3.0e38f;
#pragma unroll
                    for (int k = 0; k < KK; k++) {
                        lp[k] = fmaf(-0.5f, mah[tid * KK + k],
                                     g_logc[v * KK + k]);
                        m = fmaxf(m, lp[k]);
                    }
                    float se = 0.0f;
#pragma unroll
                    for (int k = 0; k < KK; k++) se += expf(lp[k] - m);
                    float e = -(m + logf(se));
                    out[(size_t)n * VV + v] = e;
                    if (v == 0) {
                        e_prev = e;
                    } else {
                        float mm = fminf(e_prev, e);
                        float a = expf(mm - e_prev);
                        float b = expf(mm - e);
                        float inv = 1.0f / (a + b);
                        size_t wb = (size_t)2 * Npts;
                        out[wb + (size_t)n * VV] = a * inv;
                        out[wb + (size_t)n * VV + 1] = b * inv;
                        esum += e_prev + e;
                    }
                }
            }
            __syncthreads();
        }
    }

    for (int o = 16; o; o >>= 1) esum += __shfl_xor_sync(0xffffffffu, esum, o);
    if (lane == 0) wsum[w] = esum;
    __syncthreads();
    if (tid < 8) {
        float x = wsum[tid];
        for (int o = 4; o; o >>= 1) x += __shfl_xor_sync(0x000000ffu, x, o);
        if (tid == 0) atomicAdd(&out[(size_t)4 * Npts], x);
    }
}

// ---------------------------------------------------------------------------
extern "C" void kernel_launch(void* const* d_in, const int* in_sizes, int n_in,
                              void* d_out, int out_size) {
    (void)n_in;
    (void)out_size;
    const float* z = (const float*)d_in[0];
    const float* phi = (const float*)d_in[1];
    const float* mu = (const float*)d_in[2];
    const float* sigma = (const float*)d_in[3];
    float* out = (float*)d_out;

    const int Npts = in_sizes[0] / (VV * DD);
    const int ntiles = (Npts + TN - 1) / TN;

    static int nsm = 0;
    if (nsm == 0) {
        int dev = 0;
        cudaGetDevice(&dev);
        cudaDeviceGetAttribute(&nsm, cudaDevAttrMultiProcessorCount, dev);
        if (nsm <= 0) nsm = 148;
    }

    const int SETUP_SMEM =
        (2 * DD * AST + 4 * DD + 3 * 32 * 33) * (int)sizeof(float);
    const int MAIN_SMEM = 106496;

    cudaFuncSetAttribute(setup_kernel,
                         cudaFuncAttributeMaxDynamicSharedMemorySize, SETUP_SMEM);
    cudaFuncSetAttribute(main_kernel,
                         cudaFuncAttributeMaxDynamicSharedMemorySize, MAIN_SMEM);

    setup_kernel<<<VV * KK, 512, SETUP_SMEM>>>(phi, mu, sigma, out, Npts);

    int grid = 2 * nsm;
    if (grid > ntiles) grid = ntiles;
    main_kernel<<<grid, 256, MAIN_SMEM>>>(z, out, Npts, ntiles);
}

// round 17
// speedup vs baseline: 1.2871x; 1.2871x over previous
#include <cuda_runtime.h>
#include <cuda_fp16.h>
#include <math.h>
#include <stdint.h>

#define VV 2
#define KK 8
#define DD 128
#define TN 128
#define AST 132
#define LOG2PI_F 1.8378770664093453f

__device__ uint32_t g_Bfrag[VV * KK * 9216];
__device__ float g_u[VV * KK * DD];
__device__ float g_logc[VV * KK];
__device__ float g_pen[VV * KK];
__device__ int g_ticket;

__device__ __forceinline__ void split_f16(float x, unsigned short& h, unsigned short& l) {
    __half hb = __float2half_rn(x);
    float r = x - __half2float(hb);
    __half lb = __float2half_rn(r);
    h = __half_as_ushort(hb);
    l = __half_as_ushort(lb);
}

// f16 inputs, f32 accumulate
#define MMA16816H(c, a, b)                                                     \
    asm volatile(                                                              \
        "mma.sync.aligned.m16n8k16.row.col.f32.f16.f16.f32 "                   \
        "{%0,%1,%2,%3}, {%4,%5,%6,%7}, {%8,%9}, {%0,%1,%2,%3};"                \
        : "+f"((c)[0]), "+f"((c)[1]), "+f"((c)[2]), "+f"((c)[3])               \
        : "r"((a)[0]), "r"((a)[1]), "r"((a)[2]), "r"((a)[3]),                  \
          "r"((b).x), "r"((b).y))

// ---------------------------------------------------------------------------
// setup: 512 threads. FUSED 2-COLUMN LDL^T (64 barriers; col j+1 results go
// to hazard-free Cbuf, copied back once). Blocked unit-lower inverse.
// M = D^{-1/2} Lu^{-1} folded into blobs (f16 hi/lo split).
// ---------------------------------------------------------------------------
__global__ void __launch_bounds__(512)
setup_kernel(const float* __restrict__ phi,
             const float* __restrict__ mu,
             const float* __restrict__ sigma,
             float* __restrict__ out, int Npts) {
    extern __shared__ float sm[];
    float (*A)[AST] = (float (*)[AST])sm;
    float (*M)[AST] = (float (*)[AST])(sm + DD * AST);
    float* red = sm + 2 * DD * AST;     // 128
    float* dinv = red + DD;             // 128
    float* scl = dinv + DD;             // 128
    float* mus = scl + DD;              // 128
    float* Tb = mus + DD;               // 3*1056
    float* Cbuf = Tb + 3 * 1056;        // 64*128

    const int tid = threadIdx.x;
    const int t = tid & 127;
    const int h = tid >> 7;             // 0..3
    const int v = blockIdx.x / KK;
    const int k = blockIdx.x % KK;
    const float* S = sigma + (size_t)(v * KK + k) * DD * DD;

    if (blockIdx.x == 0 && tid == 0) {
        out[(size_t)4 * Npts] = 0.0f;
        g_ticket = 0;
    }

    for (int idx = tid; idx < DD * DD; idx += 512)
        A[idx >> 7][idx & 127] = S[idx];
    __syncthreads();

    if (tid < DD) {
        float dg = A[tid][tid] + 1e-6f;
        A[tid][tid] = dg;
        red[tid] = 1.0f / (dg + 1e-12f);
    }
    __syncthreads();
    for (int s = 64; s > 0; s >>= 1) {
        if (tid < s) red[tid] += red[tid + s];
        __syncthreads();
    }
    if (tid == 0) g_pen[v * KK + k] = red[0];
    __syncthreads();

    // ---- fused 2-column LDL^T: 64 pair-steps, 1 barrier each ----
    for (int p = 0; p < DD / 2; p++) {
        const int j = 2 * p;
        const int j1 = j + 1;
        float invd1 = __fdividef(1.0f, A[j][j]);
        float aj1j = A[j1][j];
        float d2 = fmaf(-(aj1j * invd1), aj1j, A[j1][j1]);
        float invd2 = __fdividef(1.0f, d2);
        if (t > j) {
            float atj = A[t][j];
            float mf1 = -atj * invd1;
            float atj1n = fmaf(mf1, aj1j, A[t][j1]);
            if (h == 0) Cbuf[p * 128 + t] = atj1n;   // new col j+1 (side buffer)
            if (t > j1) {
                float mf2 = -atj1n * invd2;
                int n = t - j1;                       // l in (j1, t]
                int q4 = (n + 3) >> 2;
                int lo = j1 + 1 + h * q4;
                int hi = j1 + (h + 1) * q4;
                if (hi > t) hi = t;
                for (int l = lo; l <= hi; l++) {
                    float alj = A[l][j];
                    float alj1 = A[l][j1];
                    float alj1n = fmaf(-(alj * invd1), aj1j, alj1);
                    A[t][l] = A[t][l] + mf1 * alj + mf2 * alj1n;
                }
            }
        }
        __syncthreads();
    }

    // copy odd factor columns back into A
    for (int idx = tid; idx < (DD / 2) * DD; idx += 512) {
        int p = idx >> 7;
        int r = idx & 127;
        if (r > 2 * p) A[r][2 * p + 1] = Cbuf[p * 128 + r];
    }
    __syncthreads();

    if (tid < DD) {
        float d = A[tid][tid];
        red[tid] = logf(d);
        dinv[tid] = __fdividef(1.0f, d);
        scl[tid] = rsqrtf(d);
    }
    __syncthreads();
    for (int s = 64; s > 0; s >>= 1) {
        if (tid < s) red[tid] += red[tid + s];
        __syncthreads();
    }
    float logdet = fmaxf(red[0], logf(1e-6f));
    __syncthreads();

    // ---- blocked inverse of UNIT lower Lu (Lu[t][j] = A[t][j]*dinv[j]) ----
    for (int idx = tid; idx < DD * DD; idx += 512)
        M[idx >> 7][idx & 127] = 0.0f;
    __syncthreads();

    if (tid < DD) {
        const int q = tid >> 5;
        const int c = tid & 31;
        const int base = q * 32;
        M[base + c][base + c] = 1.0f;
        for (int j = c + 1; j < 32; j++) {
            float s = 0.0f;
            for (int i = c; i < j; i++)
                s = fmaf(A[base + j][base + i] * dinv[base + i],
                         M[base + i][base + c], s);
            M[base + j][base + c] = -s;
        }
    }
    __syncthreads();

    if (tid < 256) {
        const int row = tid >> 3;
        const int c0 = (tid & 7) * 4;
        for (int d = 1; d < 4; d++) {
            const int nb = 4 - d;
            for (int b = 0; b < nb; b++) {
                const int p = b + d, q = b;
                float s0 = 0.0f, s1 = 0.0f, s2 = 0.0f, s3 = 0.0f;
                for (int r = q; r < p; r++) {
#pragma unroll 8
                    for (int i = 0; i < 32; i++) {
                        float a = A[p * 32 + row][r * 32 + i] * dinv[r * 32 + i];
                        const float* mr = &M[r * 32 + i][q * 32 + c0];
                        s0 = fmaf(a, mr[0], s0);
                        s1 = fmaf(a, mr[1], s1);
                        s2 = fmaf(a, mr[2], s2);
                        s3 = fmaf(a, mr[3], s3);
                    }
                }
                float* tr = &Tb[b * 1056 + row * 33 + c0];
                tr[0] = s0; tr[1] = s1; tr[2] = s2; tr[3] = s3;
                __syncwarp();
            }
            asm volatile("bar.sync 1, 256;" ::: "memory");
            for (int b = 0; b < nb; b++) {
                const int p = b + d, q = b;
                float s0 = 0.0f, s1 = 0.0f, s2 = 0.0f, s3 = 0.0f;
                for (int i = 0; i <= row; i++) {
                    float a = M[p * 32 + row][p * 32 + i];
                    const float* tr = &Tb[b * 1056 + i * 33 + c0];
                    s0 = fmaf(a, tr[0], s0);
                    s1 = fmaf(a, tr[1], s1);
                    s2 = fmaf(a, tr[2], s2);
                    s3 = fmaf(a, tr[3], s3);
                }
                float* mr = &M[p * 32 + row][q * 32 + c0];
                mr[0] = -s0; mr[1] = -s1; mr[2] = -s2; mr[3] = -s3;
            }
            asm volatile("bar.sync 1, 256;" ::: "memory");
        }
    }
    __syncthreads();

    if (tid < DD) mus[tid] = mu[(size_t)(v * KK + k) * DD + tid];
    __syncthreads();
    if (tid < DD) {
        float u = 0.0f;
        const float4* mr = (const float4*)&M[tid][0];
        const float4* mv = (const float4*)mus;
        for (int j = 0; j < DD / 4; j++) {
            float4 a = mr[j], b = mv[j];
            u = fmaf(a.x, b.x, u);
            u = fmaf(a.y, b.y, u);
            u = fmaf(a.z, b.z, u);
            u = fmaf(a.w, b.w, u);
        }
        g_u[(size_t)(v * KK + k) * DD + tid] = u * scl[tid];
    }

    uint32_t* blob = g_Bfrag + (size_t)(v * KK + k) * 9216;
    for (int idx = tid; idx < 9216; idx += 512) {
        int reg = idx & 1;
        int lane = (idx >> 1) & 31;
        int hl = (idx >> 6) & 1;
        int ws = idx >> 7;
        int w = ws / 9;
        int s = ws - w * 9;
        int nA = (w >> 1) + 1;
        int b = (s < nA) ? w : 15 - w;
        int kb = (s < nA) ? s : s - nA;
        int col = b * 8 + (lane >> 2);
        int k0 = kb * 16 + (lane & 3) * 2 + reg * 8;
        float sc = scl[col];
        unsigned short h0, l0, h1, l1;
        split_f16(M[col][k0] * sc, h0, l0);
        split_f16(M[col][k0 + 1] * sc, h1, l1);
        blob[idx] = hl ? ((uint32_t)l0 | ((uint32_t)l1 << 16))
                       : ((uint32_t)h0 | ((uint32_t)h1 << 16));
    }

    if (tid == 0) {
        float pm = -3.0e38f;
        for (int i = 0; i < KK; i++) pm = fmaxf(pm, phi[v * KK + i]);
        float se = 0.0f;
        for (int i = 0; i < KK; i++) se += expf(phi[v * KK + i] - pm);
        float logpi = phi[v * KK + k] - pm - logf(se);
        g_logc[v * KK + k] = logpi - 0.5f * (float)DD * LOG2PI_F - 0.5f * logdet;
    }
}

// ---------------------------------------------------------------------------
// mainloop (R15 structure, f16 ops): rb in 2 chunks of 4, <=128 regs
// ---------------------------------------------------------------------------
template <int NA>
__device__ __forceinline__ void view_mainloop(
    const uint32_t* __restrict__ Bg, const uint32_t* __restrict__ Ah,
    float* __restrict__ slab, const float* __restrict__ us,
    int w, int lane) {
    constexpr int NB = 9 - NA;
    const int tq = lane & 3;
    const int tr = lane >> 2;

    uint2 BfA[NA][2], BfB[NB][2];
    {
        const uint32_t* bc = Bg + w * 9 * 128 + lane * 2;
#pragma unroll
        for (int s = 0; s < NA; s++) {
            BfA[s][0] = *(const uint2*)(bc + (s * 2 + 0) * 64);
            BfA[s][1] = *(const uint2*)(bc + (s * 2 + 1) * 64);
        }
#pragma unroll
        for (int s = 0; s < NB; s++) {
            BfB[s][0] = *(const uint2*)(bc + ((NA + s) * 2 + 0) * 64);
            BfB[s][1] = *(const uint2*)(bc + ((NA + s) * 2 + 1) * 64);
        }
    }

    for (int comp = 0; comp < KK; comp++) {
        const float* uc = us + comp * DD;
        const float uA0 = uc[w * 8 + tq * 2];
        const float uA1 = uc[w * 8 + tq * 2 + 1];
        const float uB0 = uc[(15 - w) * 8 + tq * 2];
        const float uB1 = uc[(15 - w) * 8 + tq * 2 + 1];

#pragma unroll
        for (int rbc = 0; rbc < 2; rbc++) {
            float accA[4][4], accB[4][4];
#pragma unroll
            for (int r4 = 0; r4 < 4; r4++)
#pragma unroll
                for (int r = 0; r < 4; r++) {
                    accA[r4][r] = 0.0f;
                    accB[r4][r] = 0.0f;
                }

#pragma unroll
            for (int kb = 0; kb < NB; kb++) {
                uint32_t a[4][4], al[4][4];
#pragma unroll
                for (int r4 = 0; r4 < 4; r4++) {
                    const uint32_t* ap =
                        Ah + ((rbc * 4 + r4) * 8 + kb) * 128 + lane * 4;
                    uint4 av = *(const uint4*)ap;
                    uint4 lv = *(const uint4*)(ap + 8192);
                    a[r4][0] = av.x; a[r4][1] = av.y;
                    a[r4][2] = av.z; a[r4][3] = av.w;
                    al[r4][0] = lv.x; al[r4][1] = lv.y;
                    al[r4][2] = lv.z; al[r4][3] = lv.w;
                }
#pragma unroll
                for (int r4 = 0; r4 < 4; r4++)
                    MMA16816H(accB[r4], a[r4], BfB[kb][0]);
                if (kb < NA) {
#pragma unroll
                    for (int r4 = 0; r4 < 4; r4++)
                        MMA16816H(accA[r4], a[r4], BfA[kb][0]);
                }
#pragma unroll
                for (int r4 = 0; r4 < 4; r4++)
                    MMA16816H(accB[r4], a[r4], BfB[kb][1]);
                if (kb < NA) {
#pragma unroll
                    for (int r4 = 0; r4 < 4; r4++)
                        MMA16816H(accA[r4], a[r4], BfA[kb][1]);
                }
#pragma unroll
                for (int r4 = 0; r4 < 4; r4++)
                    MMA16816H(accB[r4], al[r4], BfB[kb][0]);
                if (kb < NA) {
#pragma unroll
                    for (int r4 = 0; r4 < 4; r4++)
                        MMA16816H(accA[r4], al[r4], BfA[kb][0]);
                }
            }

#pragma unroll
            for (int r4 = 0; r4 < 4; r4++) {
                const int rb = rbc * 4 + r4;
                float d0 = accA[r4][0] - uA0;
                float d1 = accA[r4][1] - uA1;
                float d2 = accB[r4][0] - uB0;
                float d3 = accB[r4][1] - uB1;
                float s0 = d0 * d0 + d1 * d1 + d2 * d2 + d3 * d3;
                float e0 = accA[r4][2] - uA0;
                float e1 = accA[r4][3] - uA1;
                float e2 = accB[r4][2] - uB0;
                float e3 = accB[r4][3] - uB1;
                float s1 = e0 * e0 + e1 * e1 + e2 * e2 + e3 * e3;
                s0 += __shfl_xor_sync(0xffffffffu, s0, 1);
                s0 += __shfl_xor_sync(0xffffffffu, s0, 2);
                s1 += __shfl_xor_sync(0xffffffffu, s1, 1);
                s1 += __shfl_xor_sync(0xffffffffu, s1, 2);
                if (tq == 0) {
                    slab[w * 1024 + (rb * 16 + tr) * 8 + comp] = s0;
                    slab[w * 1024 + (rb * 16 + tr + 8) * 8 + comp] = s1;
                }
            }
        }

        if (comp + 1 < KK) {
            const uint32_t* bc =
                Bg + (size_t)(comp + 1) * 9216 + w * 9 * 128 + lane * 2;
#pragma unroll
            for (int s = 0; s < NA; s++) {
                BfA[s][0] = *(const uint2*)(bc + (s * 2 + 0) * 64);
                BfA[s][1] = *(const uint2*)(bc + (s * 2 + 1) * 64);
            }
#pragma unroll
            for (int s = 0; s < NB; s++) {
                BfB[s][0] = *(const uint2*)(bc + ((NA + s) * 2 + 0) * 64);
                BfB[s][1] = *(const uint2*)(bc + ((NA + s) * 2 + 1) * 64);
            }
        }
    }
}

// ---------------------------------------------------------------------------
// main (R15 exact): persistent, per-tile ticket, views fused, weights in main.
// ---------------------------------------------------------------------------
__global__ void __launch_bounds__(256, 2)
main_kernel(const float* __restrict__ z, float* __restrict__ out,
            int Npts, int ntiles) {
    extern __shared__ __align__(16) unsigned char smraw[];
    uint32_t* Ah = (uint32_t*)smraw;
    float* slab = (float*)(smraw + 65536);
    float* us = (float*)(smraw + 98304);
    float* mah = (float*)(smraw + 102400);
    __shared__ int s_tile;
    __shared__ float wsum[8];

    const int tid = threadIdx.x;
    const int w = tid >> 5;
    const int lane = tid & 31;

    if (blockIdx.x == 0 && tid == 0) {
        float p = 0.0f;
#pragma unroll
        for (int i = 0; i < VV * KK; i++) p += g_pen[i];
        out[(size_t)4 * Npts + 1] = p;
    }

    float esum = 0.0f;

    for (;;) {
        if (tid == 0) s_tile = atomicAdd(&g_ticket, 1);
        __syncthreads();
        const int tile = s_tile;
        if (tile >= ntiles) break;
        const int n0 = tile * TN;

        float e_prev = 0.0f;

        for (int v = 0; v < VV; v++) {
            const uint32_t* Bg = g_Bfrag + (size_t)v * KK * 9216;

            for (int i = tid; i < KK * DD; i += 256)
                us[i] = g_u[(size_t)v * KK * DD + i];

            const float* zr = z + (size_t)v * Npts * DD;
#pragma unroll
            for (int it = 0; it < 8; it++) {
                int idx = tid + it * 256;
                int p = idx >> 4;
                int oct = idx & 15;
                int n = n0 + p;
                float f[8];
                if (n < Npts) {
                    const float4* src =
                        (const float4*)(zr + (size_t)n * DD + oct * 8);
                    float4 a = src[0], b = src[1];
                    f[0] = a.x; f[1] = a.y; f[2] = a.z; f[3] = a.w;
                    f[4] = b.x; f[5] = b.y; f[6] = b.z; f[7] = b.w;
                } else {
#pragma unroll
                    for (int j = 0; j < 8; j++) f[j] = 0.0f;
                }
                int rb = p >> 4;
                int row_in = p & 15;
                int lane_row = row_in & 7;
                int rbit = row_in >> 3;
                int kb = oct >> 1;
                int khalf = oct & 1;
                int reg = (khalf << 1) | rbit;
                uint32_t base = (uint32_t)((rb * 8 + kb) * 128 + reg);
#pragma unroll
                for (int j = 0; j < 4; j++) {
                    unsigned short h0, l0, h1, l1;
                    split_f16(f[2 * j], h0, l0);
                    split_f16(f[2 * j + 1], h1, l1);
                    uint32_t off = base + (uint32_t)(lane_row * 4 + j) * 4;
                    Ah[off] = (uint32_t)h0 | ((uint32_t)h1 << 16);
                    Ah[off + 8192] = (uint32_t)l0 | ((uint32_t)l1 << 16);
                }
            }
            __syncthreads();

            switch (w >> 1) {
                case 0: view_mainloop<1>(Bg, Ah, slab, us, w, lane); break;
                case 1: view_mainloop<2>(Bg, Ah, slab, us, w, lane); break;
                case 2: view_mainloop<3>(Bg, Ah, slab, us, w, lane); break;
                default: view_mainloop<4>(Bg, Ah, slab, us, w, lane); break;
            }
            __syncthreads();

            for (int i = tid; i < TN * KK; i += 256) {
                float s = 0.0f;
#pragma unroll
                for (int ww = 0; ww < 8; ww++) s += slab[ww * 1024 + i];
                mah[i] = s;
            }
            __syncthreads();

            if (tid < TN) {
                int n = n0 + tid;
                if (n < Npts) {
                    float lp[KK];
                    float m = -3.0e38f;
#pragma unroll
                    for (int k = 0; k < KK; k++) {
                        lp[k] = fmaf(-0.5f, mah[tid * KK + k],
                                     g_logc[v * KK + k]);
                        m = fmaxf(m, lp[k]);
                    }
                    float se = 0.0f;
#pragma unroll
                    for (int k = 0; k < KK; k++) se += expf(lp[k] - m);
                    float e = -(m + logf(se));
                    out[(size_t)n * VV + v] = e;
                    if (v == 0) {
                        e_prev = e;
                    } else {
                        float mm = fminf(e_prev, e);
                        float a = expf(mm - e_prev);
                        float b = expf(mm - e);
                        float inv = 1.0f / (a + b);
                        size_t wb = (size_t)2 * Npts;
                        out[wb + (size_t)n * VV] = a * inv;
                        out[wb + (size_t)n * VV + 1] = b * inv;
                        esum += e_prev + e;
                    }
                }
            }
            __syncthreads();
        }
    }

    for (int o = 16; o; o >>= 1) esum += __shfl_xor_sync(0xffffffffu, esum, o);
    if (lane == 0) wsum[w] = esum;
    __syncthreads();
    if (tid < 8) {
        float x = wsum[tid];
        for (int o = 4; o; o >>= 1) x += __shfl_xor_sync(0x000000ffu, x, o);
        if (tid == 0) atomicAdd(&out[(size_t)4 * Npts], x);
    }
}

// ---------------------------------------------------------------------------
extern "C" void kernel_launch(void* const* d_in, const int* in_sizes, int n_in,
                              void* d_out, int out_size) {
    (void)n_in;
    (void)out_size;
    const float* z = (const float*)d_in[0];
    const float* phi = (const float*)d_in[1];
    const float* mu = (const float*)d_in[2];
    const float* sigma = (const float*)d_in[3];
    float* out = (float*)d_out;

    const int Npts = in_sizes[0] / (VV * DD);
    const int ntiles = (Npts + TN - 1) / TN;

    static int nsm = 0;
    if (nsm == 0) {
        int dev = 0;
        cudaGetDevice(&dev);
        cudaDeviceGetAttribute(&nsm, cudaDevAttrMultiProcessorCount, dev);
        if (nsm <= 0) nsm = 148;
    }

    const int SETUP_SMEM =
        (2 * DD * AST + 4 * DD + 3 * 1056 + 64 * 128) * (int)sizeof(float);
    const int MAIN_SMEM = 106496;

    cudaFuncSetAttribute(setup_kernel,
                         cudaFuncAttributeMaxDynamicSharedMemorySize, SETUP_SMEM);
    cudaFuncSetAttribute(main_kernel,
                         cudaFuncAttributeMaxDynamicSharedMemorySize, MAIN_SMEM);

    setup_kernel<<<VV * KK, 512, SETUP_SMEM>>>(phi, mu, sigma, out, Npts);

    int grid = 2 * nsm;
    if (grid > ntiles) grid = ntiles;
    main_kernel<<<grid, 256, MAIN_SMEM>>>(z, out, Npts, ntiles);
}